// round 15
// baseline (speedup 1.0000x reference)
#include <cuda_runtime.h>
#include <math.h>
#include <stdint.h>

// Problem constants (fixed shapes)
#define NTOK   131072      // B*T = 64*2048
#define DDIM   128
#define KCODE  512
#define TM     32          // rows per CTA
#define KC     256         // embedding codes per smem chunk
#define EP     129         // smem pitch (floats) for E chunk -> conflict-free lane reads
#define NTHR   256
#define NBLK   (NTOK / TM) // 4096

// smem layout in floats
#define SM_X    0                          // 32*128   = 4096
#define SM_S    4096                       // 32*512   = 16384
#define SM_E    (4096 + 16384)             // 256*129  = 33024
#define SM_K    (4096 + 16384 + 33024)     // 8 (per-warp KL partials)
#define SM_FLOATS (4096 + 16384 + 33024 + 8)   // 53512 floats = 214048 B

__device__ float g_e2[KCODE];
__device__ float g_avgp[KCODE];
__device__ float g_kl;

// component select (dd is a compile-time literal after unroll)
#define COMP4(v, dd) ((dd) == 0 ? (v).x : ((dd) == 1 ? (v).y : ((dd) == 2 ? (v).z : (v).w)))

// ---------------------------------------------------------------------------
// init: e2[k] = sum_d E[k][d]^2 ; zero accumulators
// ---------------------------------------------------------------------------
__global__ void vq_init(const float* __restrict__ E) {
    int k = threadIdx.x;  // 512 threads
    const float4* row = (const float4*)(E + (size_t)k * DDIM);
    float s = 0.0f;
#pragma unroll
    for (int i = 0; i < DDIM / 4; ++i) {
        float4 v = row[i];
        s = fmaf(v.x, v.x, s);
        s = fmaf(v.y, v.y, s);
        s = fmaf(v.z, v.z, s);
        s = fmaf(v.w, v.w, s);
    }
    g_e2[k]   = s;
    g_avgp[k] = 0.0f;
    if (k == 0) g_kl = 0.0f;
}

// ---------------------------------------------------------------------------
// E-chunk loader: gmem [KC x 128] -> smem pitched EP=129.
// Warp covers 4 rows x 8 float4-cols per step:
//   gmem: 4 x 128B contiguous segments (fully coalesced LDG.128)
//   smem: 4 scalar STS; bank = (R + (lane>>3) + 4*(lane&7) + dd) mod 32
//         -> (lane>>3) + 4*(lane&7) spans 0..31 -> conflict-free, aligned.
// ---------------------------------------------------------------------------
__device__ __forceinline__ void load_E_chunk(float* sE, const float* E,
                                             int ch, int wid, int lane) {
    const float4* src = (const float4*)(E + (size_t)ch * KC * DDIM);
    const int g  = lane >> 3;   // 0..3
    const int l8 = lane & 7;    // 0..7
#pragma unroll
    for (int it = 0; it < KC / (8 * 4); ++it) {          // 8 iterations
        int r = wid * (KC / 8) + it * 4 + g;             // row in chunk
        const float4* rowp = src + r * (DDIM / 4);
        float* drow = sE + r * EP;
#pragma unroll
        for (int q = 0; q < 4; ++q) {
            int c4 = l8 + 8 * q;
            float4 v = rowp[c4];
            float* dp = drow + c4 * 4;
            dp[0] = v.x; dp[1] = v.y; dp[2] = v.z; dp[3] = v.w;
        }
    }
}

// ---------------------------------------------------------------------------
// main fused kernel: logits GEMM -> softmax/KL -> gumbel softmax (encodings)
//                    -> quantized GEMM. One CTA = 32 rows.
// ---------------------------------------------------------------------------
__global__ void __launch_bounds__(NTHR, 1) vq_main(
    const float* __restrict__ X,     // [N,128]
    const float* __restrict__ U,     // [N,512]
    const float* __restrict__ E,     // [512,128]
    float* __restrict__ outQ,        // [N,128]
    float* __restrict__ outEnc)      // [N,512]
{
    extern __shared__ float sm[];
    float* sX = sm + SM_X;
    float* sS = sm + SM_S;
    float* sE = sm + SM_E;
    float* sK = sm + SM_K;

    const int tid  = threadIdx.x;
    const int wid  = tid >> 5;   // 0..7
    const int lane = tid & 31;
    const int row0 = blockIdx.x * TM;

    // ---- load X tile [32 x 128] (coalesced float4, pitch 128 -> aligned) ----
    {
        const float4* src = (const float4*)(X + (size_t)row0 * DDIM);
        float4* dst = (float4*)sX;
#pragma unroll
        for (int i = 0; i < (TM * DDIM / 4) / NTHR; ++i)
            dst[tid + NTHR * i] = src[tid + NTHR * i];
    }

    // =====================================================================
    // Phase 1: logits  l'[r][k] = 2 * (x_r . e_k) - e2[k]
    // thread (wid,lane): rows wid*4+i (i<4), codes lane+32*j (j<8) per chunk
    // =====================================================================
    for (int ch = 0; ch < KCODE / KC; ++ch) {
        __syncthreads();  // X ready (ch=0) / previous chunk compute done
        load_E_chunk(sE, E, ch, wid, lane);
        __syncthreads();

        float acc[4][8];
#pragma unroll
        for (int i = 0; i < 4; ++i)
#pragma unroll
            for (int j = 0; j < 8; ++j) acc[i][j] = 0.0f;

        const float* xp = sX + (wid * 4) * DDIM;
        const float* ep = sE + lane * EP;

#pragma unroll 2
        for (int d = 0; d < DDIM; d += 4) {
            float4 xv0 = *(const float4*)(xp + 0 * DDIM + d);
            float4 xv1 = *(const float4*)(xp + 1 * DDIM + d);
            float4 xv2 = *(const float4*)(xp + 2 * DDIM + d);
            float4 xv3 = *(const float4*)(xp + 3 * DDIM + d);
#pragma unroll
            for (int dd = 0; dd < 4; ++dd) {
                float ev[8];
#pragma unroll
                for (int j = 0; j < 8; ++j) ev[j] = ep[j * (32 * EP) + d + dd];
                float x0 = COMP4(xv0, dd), x1 = COMP4(xv1, dd);
                float x2 = COMP4(xv2, dd), x3 = COMP4(xv3, dd);
#pragma unroll
                for (int j = 0; j < 8; ++j) {
                    acc[0][j] = fmaf(x0, ev[j], acc[0][j]);
                    acc[1][j] = fmaf(x1, ev[j], acc[1][j]);
                    acc[2][j] = fmaf(x2, ev[j], acc[2][j]);
                    acc[3][j] = fmaf(x3, ev[j], acc[3][j]);
                }
            }
        }
        // epilogue: l' = 2*dot - e2
#pragma unroll
        for (int j = 0; j < 8; ++j) {
            int k = ch * KC + lane + 32 * j;
            float e2k = g_e2[k];
#pragma unroll
            for (int i = 0; i < 4; ++i)
                sS[(wid * 4 + i) * KCODE + k] = fmaf(2.0f, acc[i][j], -e2k);
        }
    }
    // NOTE: each thread reads back exactly the sS entries it wrote (same
    // (wid,lane) partition) -> no __syncthreads needed before phase 2.
    // sE still holds chunk 1 -- phase 3 exploits this (order {1,0}).

    // =====================================================================
    // Phase 2: per-row softmax stats (KL) + gumbel-relaxed softmax encodings
    // warp wid handles rows wid*4 .. wid*4+3 ; lane owns cols lane+32*i
    // =====================================================================
    float csum[16];
#pragma unroll
    for (int i = 0; i < 16; ++i) csum[i] = 0.0f;
    float klacc = 0.0f;

    const float U_LO = 1.17549435e-38f;                 // f32 tiny (jnp.finfo.tiny)
    const float U_HI = __uint_as_float(0x3F7FFFFEu);    // f32(1 - 1e-7)

    for (int rr = 0; rr < 4; ++rr) {
        const int r = wid * 4 + rr;
        float* Sr = sS + r * KCODE;
        float lv[16], tt[16];
#pragma unroll
        for (int i = 0; i < 16; ++i) lv[i] = Sr[lane + 32 * i];

        // --- log-softmax stats: m, s, and Sum p*log(K*p) (cancellation-free) ---
        float m = lv[0];
#pragma unroll
        for (int i = 1; i < 16; ++i) m = fmaxf(m, lv[i]);
#pragma unroll
        for (int o = 16; o > 0; o >>= 1) m = fmaxf(m, __shfl_xor_sync(0xffffffffu, m, o));

        float s = 0.0f;
#pragma unroll
        for (int i = 0; i < 16; ++i) { tt[i] = __expf(lv[i] - m); s += tt[i]; }
#pragma unroll
        for (int o = 16; o > 0; o >>= 1) s += __shfl_xor_sync(0xffffffffu, s, o);

        float lsK = logf(s * (1.0f / (float)KCODE));    // log(s/K): exact /512 scaling
        float w = 0.0f;
#pragma unroll
        for (int i = 0; i < 16; ++i) w = fmaf(tt[i], (lv[i] - m) - lsK, w);
#pragma unroll
        for (int o = 16; o > 0; o >>= 1) w += __shfl_xor_sync(0xffffffffu, w, o);
        klacc += w / s;   // = Sum_k p*(logp + logK) for this row

        // --- gumbel + relaxed softmax:  a = (l' + g) / tau = 2*(l' + g) ---
        const float* Ur = U + (size_t)(row0 + r) * KCODE;
        float m2 = -3.4e38f;
#pragma unroll
        for (int i = 0; i < 16; ++i) {
            float u = Ur[lane + 32 * i];
            u = fminf(fmaxf(u, U_LO), U_HI);
            // accurate log(u) even near 1 (immune to fast-math lg2.approx)
            float lg = (u > 0.6f) ? log1pf(u - 1.0f) : logf(u);
            float g  = -logf(-lg);
            float a  = 2.0f * (lv[i] + g);
            lv[i] = a;
            m2 = fmaxf(m2, a);
        }
#pragma unroll
        for (int o = 16; o > 0; o >>= 1) m2 = fmaxf(m2, __shfl_xor_sync(0xffffffffu, m2, o));

        float s2 = 0.0f;
#pragma unroll
        for (int i = 0; i < 16; ++i) { tt[i] = __expf(lv[i] - m2); s2 += tt[i]; }
#pragma unroll
        for (int o = 16; o > 0; o >>= 1) s2 += __shfl_xor_sync(0xffffffffu, s2, o);

        float inv = 1.0f / s2;
        float* Or = outEnc + (size_t)(row0 + r) * KCODE;
#pragma unroll
        for (int i = 0; i < 16; ++i) {
            float e = tt[i] * inv;
            Sr[lane + 32 * i] = e;      // keep for GEMM2
            Or[lane + 32 * i] = e;      // stream encodings out (coalesced)
            csum[i] += e;
        }
    }

    // ---- CTA reductions: column sums (avg_probs) and KL partial ----
    // sX region reused (X tile dead); klacc in dedicated sK (keeps sE intact!)
#pragma unroll
    for (int i = 0; i < 16; ++i) sX[wid * KCODE / 8 * 8 + 0] = sX[wid * KCODE + 0], csum[i] = csum[i]; // (no-op guard removed below)
#pragma unroll
    for (int i = 0; i < 16; ++i) sX[wid * KCODE + lane + 32 * i] = csum[i];
    // NOTE: 8*KCODE = 4096 floats == exactly the sX region
    if (lane == 0) sK[wid] = klacc;
    __syncthreads();
#pragma unroll
    for (int c0 = 0; c0 < KCODE / NTHR; ++c0) {
        int c = tid + NTHR * c0;
        float v = 0.0f;
#pragma unroll
        for (int w8 = 0; w8 < 8; ++w8) v += sX[w8 * KCODE + c];
        atomicAdd(&g_avgp[c], v);
    }
    if (tid == 0) {
        float kt = 0.0f;
#pragma unroll
        for (int w8 = 0; w8 < 8; ++w8) kt += sK[w8];
        atomicAdd(&g_kl, kt);
    }

    // =====================================================================
    // Phase 3: quantized  Q[32,128] = Enc[32,512] @ E[512,128]
    // chunk order {1,0}: chunk 1 is still resident in sE from phase 1.
    // thread (wid,lane): rows wid*4+i, dcols lane+32*j (j<4)
    // =====================================================================
    float q[4][4];
#pragma unroll
    for (int i = 0; i < 4; ++i)
#pragma unroll
        for (int j = 0; j < 4; ++j) q[i][j] = 0.0f;

    for (int cc = 0; cc < KCODE / KC; ++cc) {
        const int ch = (KCODE / KC - 1) - cc;   // 1, then 0
        if (cc > 0) {
            __syncthreads();        // everyone done reading previous chunk
            load_E_chunk(sE, E, ch, wid, lane);
            __syncthreads();
        }
        // cc==0: resident chunk; ordering provided by the reduction's syncthreads.

        const float* encp = sS + (wid * 4) * KCODE + ch * KC;
#pragma unroll 2
        for (int kk = 0; kk < KC; kk += 4) {
            float4 av0 = *(const float4*)(encp + 0 * KCODE + kk);
            float4 av1 = *(const float4*)(encp + 1 * KCODE + kk);
            float4 av2 = *(const float4*)(encp + 2 * KCODE + kk);
            float4 av3 = *(const float4*)(encp + 3 * KCODE + kk);
#pragma unroll
            for (int dd = 0; dd < 4; ++dd) {
                float ev[4];
#pragma unroll
                for (int j = 0; j < 4; ++j) ev[j] = sE[(kk + dd) * EP + lane + 32 * j];
                float a0 = COMP4(av0, dd), a1 = COMP4(av1, dd);
                float a2 = COMP4(av2, dd), a3 = COMP4(av3, dd);
#pragma unroll
                for (int j = 0; j < 4; ++j) {
                    q[0][j] = fmaf(a0, ev[j], q[0][j]);
                    q[1][j] = fmaf(a1, ev[j], q[1][j]);
                    q[2][j] = fmaf(a2, ev[j], q[2][j]);
                    q[3][j] = fmaf(a3, ev[j], q[3][j]);
                }
            }
        }
    }
    // write quantized (straight-through estimator is numerically identity)
#pragma unroll
    for (int i = 0; i < 4; ++i) {
        float* Qr = outQ + (size_t)(row0 + wid * 4 + i) * DDIM;
#pragma unroll
        for (int j = 0; j < 4; ++j) Qr[lane + 32 * j] = q[i][j];
    }
}

// ---------------------------------------------------------------------------
// finalize: KL scalar and perplexity
// ---------------------------------------------------------------------------
__global__ void vq_finalize(float* __restrict__ d_out) {
    __shared__ float red[KCODE];
    int t = threadIdx.x;  // 512
    float ap = g_avgp[t] * (1.0f / (float)NTOK);
    red[t] = ap * logf(ap + 1e-10f);
    __syncthreads();
    for (int s = KCODE / 2; s > 0; s >>= 1) {
        if (t < s) red[t] += red[t + s];
        __syncthreads();
    }
    if (t == 0) {
        d_out[0] = g_kl * (1.0f / (float)KCODE);                  // KL
        d_out[1 + (size_t)NTOK * DDIM] = expf(-red[0]);           // perplexity
    }
}

// ---------------------------------------------------------------------------
// Output layout (tuple order, row-major):
//   [0]                      KL (scalar)
//   [1 .. 1+N*D)             quantized [64,2048,128]
//   [1+N*D]                  perplexity (scalar)
//   [2+N*D .. 2+N*D+N*K)     encodings [N,512]
// ---------------------------------------------------------------------------
extern "C" void kernel_launch(void* const* d_in, const int* in_sizes, int n_in,
                              void* d_out, int out_size) {
    const float* X = (const float*)d_in[0];   // inputs  [64,2048,128]
    const float* U = (const float*)d_in[1];   // u       [131072,512]
    const float* E = (const float*)d_in[2];   // embedding [512,128]
    float* out = (float*)d_out;

    float* outQ   = out + 1;
    float* outEnc = out + 2 + (size_t)NTOK * DDIM;

    cudaFuncSetAttribute(vq_main, cudaFuncAttributeMaxDynamicSharedMemorySize,
                         SM_FLOATS * (int)sizeof(float));

    vq_init<<<1, KCODE>>>(E);
    vq_main<<<NBLK, NTHR, SM_FLOATS * sizeof(float)>>>(X, U, E, outQ, outEnc);
    vq_finalize<<<1, KCODE>>>(out);
}

// round 17
// speedup vs baseline: 1.3933x; 1.3933x over previous
#include <cuda_runtime.h>
#include <math.h>
#include <stdint.h>

// Problem constants (fixed shapes)
#define NTOK   131072      // B*T = 64*2048
#define DDIM   128
#define KCODE  512
#define TM     32          // rows per CTA
#define KC     256         // embedding codes per smem chunk
#define EP     130         // smem pitch (floats): EVEN (float2-aligned), 65 (8B) == 1 mod 16 -> conflict-free LDS.64
#define NTHR   512
#define NBLK   (NTOK / TM) // 4096

// smem layout in floats
#define SM_X    0                          // 32*128   = 4096
#define SM_S    4096                       // 32*512   = 16384
#define SM_E    (4096 + 16384)             // 256*130  = 33280
#define SM_K    (4096 + 16384 + 33280)     // 16 (per-warp KL partials)
#define SM_FLOATS (4096 + 16384 + 33280 + 16)   // 53784 floats = 215136 B

__device__ float g_e2[KCODE];
__device__ float g_avgp[KCODE];
__device__ float g_kl;

// component select (dd is a compile-time literal after unroll)
#define COMP4(v, dd) ((dd) == 0 ? (v).x : ((dd) == 1 ? (v).y : ((dd) == 2 ? (v).z : (v).w)))

// ---- packed f32x2 helpers (FFMA2: 2x FP32 FMA throughput; PTX-only) ----
__device__ __forceinline__ void ffma2(uint64_t& d, uint64_t a, uint64_t b) {
    asm("fma.rn.f32x2 %0, %1, %2, %0;" : "+l"(d) : "l"(a), "l"(b));
}
__device__ __forceinline__ uint64_t packbc(float v) {   // (v, v)
    uint64_t r;
    uint32_t u = __float_as_uint(v);
    asm("mov.b64 %0, {%1, %1};" : "=l"(r) : "r"(u));
    return r;
}
__device__ __forceinline__ float hsum2(uint64_t v) {    // .x + .y
    uint32_t lo, hi;
    asm("mov.b64 {%0, %1}, %2;" : "=r"(lo), "=r"(hi) : "l"(v));
    return __uint_as_float(lo) + __uint_as_float(hi);
}
__device__ __forceinline__ void unpack2(uint64_t v, float& a, float& b) {
    uint32_t lo, hi;
    asm("mov.b64 {%0, %1}, %2;" : "=r"(lo), "=r"(hi) : "l"(v));
    a = __uint_as_float(lo);
    b = __uint_as_float(hi);
}

// ---------------------------------------------------------------------------
// init: e2[k] = sum_d E[k][d]^2 ; zero accumulators
// ---------------------------------------------------------------------------
__global__ void vq_init(const float* __restrict__ E) {
    int k = threadIdx.x;  // 512 threads
    const float4* row = (const float4*)(E + (size_t)k * DDIM);
    float s = 0.0f;
#pragma unroll
    for (int i = 0; i < DDIM / 4; ++i) {
        float4 v = row[i];
        s = fmaf(v.x, v.x, s);
        s = fmaf(v.y, v.y, s);
        s = fmaf(v.z, v.z, s);
        s = fmaf(v.w, v.w, s);
    }
    g_e2[k]   = s;
    g_avgp[k] = 0.0f;
    if (k == 0) g_kl = 0.0f;
}

// ---------------------------------------------------------------------------
// E-chunk loader: gmem [KC x 128] -> smem pitched EP=130, float2 granularity.
// linear float2 index: row = lin>>6, c2 = lin&63.
//   gmem: consecutive lanes -> consecutive float2 (perfect LDG.64 coalescing)
//   smem: 8B-addr = row*65 + c2; per 16-lane phase c2 contiguous -> optimal
// ---------------------------------------------------------------------------
__device__ __forceinline__ void load_E_chunk(float* sE, const float* E,
                                             int ch, int tid) {
    const float2* src = (const float2*)(E + (size_t)ch * KC * DDIM);
#pragma unroll
    for (int i = 0; i < (KC * DDIM / 2) / NTHR; ++i) {   // 32 iterations
        int lin = tid + NTHR * i;
        int r   = lin >> 6;        // 64 float2 per row
        int c2  = lin & 63;
        float2 v = src[lin];
        *(float2*)(sE + r * EP + 2 * c2) = v;
    }
}

// ---------------------------------------------------------------------------
// main fused kernel: logits GEMM -> softmax/KL -> gumbel softmax (encodings)
//                    -> quantized GEMM. One CTA = 32 rows, 16 warps.
// ---------------------------------------------------------------------------
__global__ void __launch_bounds__(NTHR, 1) vq_main(
    const float* __restrict__ X,     // [N,128]
    const float* __restrict__ U,     // [N,512]
    const float* __restrict__ E,     // [512,128]
    float* __restrict__ outQ,        // [N,128]  (base only 4B-aligned! scalar stores)
    float* __restrict__ outEnc)      // [N,512]
{
    extern __shared__ float sm[];
    float* sX = sm + SM_X;
    float* sS = sm + SM_S;
    float* sE = sm + SM_E;
    float* sK = sm + SM_K;

    const int tid  = threadIdx.x;
    const int wid  = tid >> 5;   // 0..15
    const int lane = tid & 31;
    const int row0 = blockIdx.x * TM;

    // ---- load X tile [32 x 128] (coalesced float4) ----
    {
        const float4* src = (const float4*)(X + (size_t)row0 * DDIM);
        float4* dst = (float4*)sX;
#pragma unroll
        for (int i = 0; i < (TM * DDIM / 4) / NTHR; ++i)
            dst[tid + NTHR * i] = src[tid + NTHR * i];
    }

    // =====================================================================
    // Phase 1: logits  l'[r][k] = 2 * (x_r . e_k) - e2[k]
    // warp wid: rows wid*2 + i (i<2); lane: codes lane+32*j (j<8) per chunk.
    // FFMA2 packed over d-pairs: x-pair and e-pair are contiguous float2.
    // =====================================================================
    for (int ch = 0; ch < KCODE / KC; ++ch) {
        __syncthreads();  // X ready (ch=0) / previous chunk compute done
        load_E_chunk(sE, E, ch, tid);
        __syncthreads();

        uint64_t acc[2][8];
#pragma unroll
        for (int i = 0; i < 2; ++i)
#pragma unroll
            for (int j = 0; j < 8; ++j) acc[i][j] = 0ull;

        const float* xp = sX + (wid * 2) * DDIM;
        const float* ep = sE + lane * EP;

#pragma unroll 2
        for (int d = 0; d < DDIM; d += 2) {
            uint64_t a0 = *(const uint64_t*)(xp + d);
            uint64_t a1 = *(const uint64_t*)(xp + DDIM + d);
#pragma unroll
            for (int j = 0; j < 8; ++j) {
                uint64_t e = *(const uint64_t*)(ep + j * (32 * EP) + d);
                ffma2(acc[0][j], a0, e);
                ffma2(acc[1][j], a1, e);
            }
        }
        // epilogue: l' = 2*dot - e2
#pragma unroll
        for (int j = 0; j < 8; ++j) {
            int k = ch * KC + lane + 32 * j;
            float e2k = g_e2[k];
#pragma unroll
            for (int i = 0; i < 2; ++i)
                sS[(wid * 2 + i) * KCODE + k] = fmaf(2.0f, hsum2(acc[i][j]), -e2k);
        }
    }
    // NOTE: each thread reads back exactly the sS entries it wrote (same
    // (wid,lane) partition) -> no __syncthreads needed before phase 2.
    // sE still holds chunk 1 -- phase 3 exploits this (order {1,0}).

    // =====================================================================
    // Phase 2: per-row softmax stats (KL) + gumbel-relaxed softmax encodings
    // warp wid: rows wid*2, wid*2+1 ; lane owns cols lane+32*i
    // =====================================================================
    float csum[16];
#pragma unroll
    for (int i = 0; i < 16; ++i) csum[i] = 0.0f;
    float klacc = 0.0f;

    const float U_LO = 1.17549435e-38f;                 // f32 tiny (jnp.finfo.tiny)
    const float U_HI = __uint_as_float(0x3F7FFFFEu);    // f32(1 - 1e-7)

    for (int rr = 0; rr < 2; ++rr) {
        const int r = wid * 2 + rr;
        float* Sr = sS + r * KCODE;
        float lv[16], tt[16];
#pragma unroll
        for (int i = 0; i < 16; ++i) lv[i] = Sr[lane + 32 * i];

        // --- log-softmax stats: m, s, and Sum p*log(K*p) (cancellation-free) ---
        float m = lv[0];
#pragma unroll
        for (int i = 1; i < 16; ++i) m = fmaxf(m, lv[i]);
#pragma unroll
        for (int o = 16; o > 0; o >>= 1) m = fmaxf(m, __shfl_xor_sync(0xffffffffu, m, o));

        float s = 0.0f;
#pragma unroll
        for (int i = 0; i < 16; ++i) { tt[i] = __expf(lv[i] - m); s += tt[i]; }
#pragma unroll
        for (int o = 16; o > 0; o >>= 1) s += __shfl_xor_sync(0xffffffffu, s, o);

        float lsK = logf(s * (1.0f / (float)KCODE));    // log(s/K): exact /512 scaling
        float w = 0.0f;
#pragma unroll
        for (int i = 0; i < 16; ++i) w = fmaf(tt[i], (lv[i] - m) - lsK, w);
#pragma unroll
        for (int o = 16; o > 0; o >>= 1) w += __shfl_xor_sync(0xffffffffu, w, o);
        klacc += w / s;   // = Sum_k p*(logp + logK) for this row

        // --- gumbel + relaxed softmax:  a = (l' + g) / tau = 2*(l' + g) ---
        const float* Ur = U + (size_t)(row0 + r) * KCODE;
        float m2 = -3.4e38f;
#pragma unroll
        for (int i = 0; i < 16; ++i) {
            float u = Ur[lane + 32 * i];
            u = fminf(fmaxf(u, U_LO), U_HI);
            // accurate log(u) near 1 (log1pf Sterbenz-exact); fast path below
            float lg = (u > 0.6f) ? log1pf(u - 1.0f) : __logf(u);
            float g  = -__logf(-lg);
            float a  = 2.0f * (lv[i] + g);
            lv[i] = a;
            m2 = fmaxf(m2, a);
        }
#pragma unroll
        for (int o = 16; o > 0; o >>= 1) m2 = fmaxf(m2, __shfl_xor_sync(0xffffffffu, m2, o));

        float s2 = 0.0f;
#pragma unroll
        for (int i = 0; i < 16; ++i) { tt[i] = __expf(lv[i] - m2); s2 += tt[i]; }
#pragma unroll
        for (int o = 16; o > 0; o >>= 1) s2 += __shfl_xor_sync(0xffffffffu, s2, o);

        float inv = 1.0f / s2;
        float* Or = outEnc + (size_t)(row0 + r) * KCODE;
#pragma unroll
        for (int i = 0; i < 16; ++i) {
            float e = tt[i] * inv;
            Sr[lane + 32 * i] = e;      // keep for GEMM2
            Or[lane + 32 * i] = e;      // stream encodings out (coalesced)
            csum[i] += e;
        }
    }

    // ---- CTA reductions: column sums (avg_probs) and KL partial ----
    // sX reused (X tile dead, 8*512 floats); two-step for 16 warps.
    if (wid < 8) {
#pragma unroll
        for (int i = 0; i < 16; ++i) sX[wid * KCODE + lane + 32 * i] = csum[i];
    }
    if (lane == 0) sK[wid] = klacc;
    __syncthreads();
    if (wid >= 8) {
#pragma unroll
        for (int i = 0; i < 16; ++i) sX[(wid - 8) * KCODE + lane + 32 * i] += csum[i];
    }
    __syncthreads();
    {
        int c = tid;   // 512 threads, 512 cols
        float v = 0.0f;
#pragma unroll
        for (int w8 = 0; w8 < 8; ++w8) v += sX[w8 * KCODE + c];
        atomicAdd(&g_avgp[c], v);
    }
    if (tid == 0) {
        float kt = 0.0f;
#pragma unroll
        for (int w16 = 0; w16 < 16; ++w16) kt += sK[w16];
        atomicAdd(&g_kl, kt);
    }

    // =====================================================================
    // Phase 3: quantized  Q[32,128] = Enc[32,512] @ E[512,128]
    // chunk order {1,0}: chunk 1 still resident in sE from phase 1.
    // warp wid: rows wid*2+i ; lane: dcol pairs 2*lane + {0,1} + 64*j2 (j2<2)
    // FFMA2 packed over dcol-pairs: E-pair contiguous float2 in row-major sE.
    // =====================================================================
    uint64_t q2[2][2];
#pragma unroll
    for (int i = 0; i < 2; ++i)
#pragma unroll
        for (int j = 0; j < 2; ++j) q2[i][j] = 0ull;

    for (int cc = 0; cc < KCODE / KC; ++cc) {
        const int ch = (KCODE / KC - 1) - cc;   // 1, then 0
        if (cc > 0) {
            __syncthreads();        // everyone done reading previous chunk
            load_E_chunk(sE, E, ch, tid);
            __syncthreads();
        }
        // cc==0: resident chunk; ordering provided by the reduction syncthreads.

        const float* encp = sS + (wid * 2) * KCODE + ch * KC;
        const float* eb   = sE + 2 * lane;
#pragma unroll 2
        for (int kk = 0; kk < KC; kk += 4) {
            float4 av0 = *(const float4*)(encp + kk);
            float4 av1 = *(const float4*)(encp + KCODE + kk);
#pragma unroll
            for (int dd = 0; dd < 4; ++dd) {
                uint64_t e0 = *(const uint64_t*)(eb + (kk + dd) * EP);
                uint64_t e1 = *(const uint64_t*)(eb + (kk + dd) * EP + 64);
                uint64_t a0 = packbc(COMP4(av0, dd));
                uint64_t a1 = packbc(COMP4(av1, dd));
                ffma2(q2[0][0], a0, e0);
                ffma2(q2[0][1], a0, e1);
                ffma2(q2[1][0], a1, e0);
                ffma2(q2[1][1], a1, e1);
            }
        }
    }
    // write quantized. outQ base is d_out+1 (4B-aligned only) -> SCALAR stores.
    // Lanes still cover contiguous 256B segments; 4B coalescing is fine here
    // (epilogue is <1% of kernel time).
#pragma unroll
    for (int i = 0; i < 2; ++i) {
        float* Qr = outQ + (size_t)(row0 + wid * 2 + i) * DDIM;
        float v0, v1;
        unpack2(q2[i][0], v0, v1);
        Qr[2 * lane]     = v0;
        Qr[2 * lane + 1] = v1;
        unpack2(q2[i][1], v0, v1);
        Qr[2 * lane + 64] = v0;
        Qr[2 * lane + 65] = v1;
    }
}

// ---------------------------------------------------------------------------
// finalize: KL scalar and perplexity
// ---------------------------------------------------------------------------
__global__ void vq_finalize(float* __restrict__ d_out) {
    __shared__ float red[KCODE];
    int t = threadIdx.x;  // 512
    float ap = g_avgp[t] * (1.0f / (float)NTOK);
    red[t] = ap * logf(ap + 1e-10f);
    __syncthreads();
    for (int s = KCODE / 2; s > 0; s >>= 1) {
        if (t < s) red[t] += red[t + s];
        __syncthreads();
    }
    if (t == 0) {
        d_out[0] = g_kl * (1.0f / (float)KCODE);                  // KL
        d_out[1 + (size_t)NTOK * DDIM] = expf(-red[0]);           // perplexity
    }
}

// ---------------------------------------------------------------------------
// Output layout (tuple order, row-major):
//   [0]                      KL (scalar)
//   [1 .. 1+N*D)             quantized [64,2048,128]
//   [1+N*D]                  perplexity (scalar)
//   [2+N*D .. 2+N*D+N*K)     encodings [N,512]
// ---------------------------------------------------------------------------
extern "C" void kernel_launch(void* const* d_in, const int* in_sizes, int n_in,
                              void* d_out, int out_size) {
    const float* X = (const float*)d_in[0];   // inputs  [64,2048,128]
    const float* U = (const float*)d_in[1];   // u       [131072,512]
    const float* E = (const float*)d_in[2];   // embedding [512,128]
    float* out = (float*)d_out;

    float* outQ   = out + 1;
    float* outEnc = out + 2 + (size_t)NTOK * DDIM;

    cudaFuncSetAttribute(vq_main, cudaFuncAttributeMaxDynamicSharedMemorySize,
                         SM_FLOATS * (int)sizeof(float));

    vq_init<<<1, KCODE>>>(E);
    vq_main<<<NBLK, NTHR, SM_FLOATS * sizeof(float)>>>(X, U, E, outQ, outEnc);
    vq_finalize<<<1, KCODE>>>(out);
}